// round 15
// baseline (speedup 1.0000x reference)
#include <cuda_runtime.h>
#include <cuda_bf16.h>
#include <cuda_fp16.h>
#include <cstdint>
#include <cstddef>

// Problem constants
#define NB    32
#define NN    512
#define DIN_  64
#define DOUT_ 64
#define ET_   32
#define CHEB  3
#define KI_   (CHEB * DIN_)   // 192

// Scratch: h[b][k][n][i]  fp32 (12.6 MB)
__device__ float g_h[(size_t)NB * CHEB * NN * DIN_];
// Pre-converted W (+bias as chunk 96), KC-MAJOR: c = kc*32 + d, bias at 96.
// fp16: [97 chunks][64 rows][72 cols] (144B rows). Written by prop_mma<0>.
__device__ __align__(16) __half g_Ws[97 * 64 * 72];

#define TSTR 144u   // tile row stride bytes (odd multiple of 16B)

// ===========================================================================
// PTX helpers
// ===========================================================================
__device__ __forceinline__ uint32_t smem_u32(const void* p) {
    uint32_t a;
    asm("{ .reg .u64 t; cvta.to.shared.u64 t, %1; cvt.u32.u64 %0, t; }"
        : "=r"(a) : "l"(p));
    return a;
}
__device__ __forceinline__ void ldsm_x4(uint32_t& r0, uint32_t& r1,
                                        uint32_t& r2, uint32_t& r3, uint32_t addr) {
    asm volatile("ldmatrix.sync.aligned.m8n8.x4.shared.b16 {%0,%1,%2,%3}, [%4];"
                 : "=r"(r0), "=r"(r1), "=r"(r2), "=r"(r3) : "r"(addr));
}
__device__ __forceinline__ void ldsm_x4t(uint32_t& r0, uint32_t& r1,
                                         uint32_t& r2, uint32_t& r3, uint32_t addr) {
    asm volatile("ldmatrix.sync.aligned.m8n8.x4.trans.shared.b16 {%0,%1,%2,%3}, [%4];"
                 : "=r"(r0), "=r"(r1), "=r"(r2), "=r"(r3) : "r"(addr));
}
__device__ __forceinline__ void mma_fp16(float* c, const uint32_t* a,
                                         uint32_t b0, uint32_t b1) {
    asm volatile(
        "mma.sync.aligned.m16n8k16.row.col.f32.f16.f16.f32 "
        "{%0,%1,%2,%3}, {%4,%5,%6,%7}, {%8,%9}, {%0,%1,%2,%3};"
        : "+f"(c[0]), "+f"(c[1]), "+f"(c[2]), "+f"(c[3])
        : "r"(a[0]), "r"(a[1]), "r"(a[2]), "r"(a[3]), "r"(b0), "r"(b1));
}
__device__ __forceinline__ void cp16(uint32_t dst, const void* src) {
    asm volatile("cp.async.ca.shared.global [%0], [%1], 16;" :: "r"(dst), "l"(src));
}
#define CP_COMMIT() asm volatile("cp.async.commit_group;" ::: "memory")
#define CP_WAIT1()  asm volatile("cp.async.wait_group 1;" ::: "memory")
__device__ __forceinline__ void bar_sync(int id) {
    asm volatile("bar.sync %0, 256;" :: "r"(id) : "memory");
}
__device__ __forceinline__ void bar_arrive(int id) {
    asm volatile("bar.arrive %0, 256;" :: "r"(id) : "memory");
}
#define BAR_FULL  1
#define BAR_EMPTY 3

// fp16 pack
__device__ __forceinline__ uint32_t pack2h(float p0, float p1) {
    uint32_t r;
    asm("cvt.rn.f16x2.f32 %0, %1, %2;" : "=r"(r) : "f"(p1), "f"(p0));
    return r;
}

// ===========================================================================
// Prop kernels (unchanged, validated): single-product fp16, warp-specialized,
// 2 CTAs/SM. C[512x64] = A[512x512] @ Bm[512x64].
// MODE 0 also converts W (+bias) tiles into g_Ws on idle consumer warps.
// smem: 2 buffers x {A 18432 | B 9216} = 55296 B
// ===========================================================================
#define BUFSZ   27648
#define OB_B    18432
#define P_SMEM  (2 * BUFSZ)

__device__ __forceinline__ void mma_chunk_h(float acc[2][8][4],
                                            uint32_t aBase, uint32_t bBase,
                                            int warp, int lane) {
    const uint32_t rowSel = (uint32_t)(warp * 32 + (lane & 15));
    const uint32_t kSel   = (uint32_t)((lane >> 4) << 3);
    const uint32_t bRow   = (uint32_t)((lane & 7) + (((lane >> 3) & 1) << 3));
    const uint32_t bCol   = (uint32_t)((lane >> 4) << 3);
    #pragma unroll
    for (int ks = 0; ks < 4; ++ks) {
        const uint32_t kb = (uint32_t)(ks * 16);
        uint32_t ah[2][4];
        #pragma unroll
        for (int mt = 0; mt < 2; ++mt) {
            const uint32_t off = (rowSel + (uint32_t)(mt * 16)) * TSTR + (kb + kSel) * 2u;
            ldsm_x4(ah[mt][0], ah[mt][1], ah[mt][2], ah[mt][3], aBase + off);
        }
        #pragma unroll
        for (int g = 0; g < 4; ++g) {
            const uint32_t boff = (kb + bRow) * TSTR + ((uint32_t)(g * 16) + bCol) * 2u;
            uint32_t b0, b1, b2, b3;
            ldsm_x4t(b0, b1, b2, b3, bBase + boff);
            #pragma unroll
            for (int mt = 0; mt < 2; ++mt) {
                mma_fp16(acc[mt][2 * g],     ah[mt], b0, b1);
                mma_fp16(acc[mt][2 * g + 1], ah[mt], b2, b3);
            }
        }
    }
}

template<int MODE>
__global__ __launch_bounds__(256, 2) void prop_mma(
    const float* __restrict__ R,
    const float* __restrict__ SC,
    const float* __restrict__ X,
    const float* __restrict__ Wp,
    const float* __restrict__ biasp)
{
    extern __shared__ char smem[];
    const int b = blockIdx.y;
    const int rowBlk = blockIdx.x * 128;

    float* hb = g_h + (size_t)b * (CHEB * NN * DIN_);
    const float* A;
    const float* Bm;
    const float* Sub = nullptr;
    float* C;
    if (MODE == 0) {
        const int which = blockIdx.z;
        A  = (which == 0 ? SC : R) + (size_t)b * NN * NN;
        Bm = X + (size_t)b * NN * DIN_;
        C  = hb + (size_t)which * NN * DIN_;
    } else {
        A   = R  + (size_t)b * NN * NN;
        Bm  = hb + (size_t)1 * NN * DIN_;
        Sub = hb + (size_t)0 * NN * DIN_;
        C   = hb + (size_t)2 * NN * DIN_;
    }

    const int t    = threadIdx.x;
    const int wid  = t >> 5;
    const int lane = t & 31;
    const uint32_t sb = smem_u32(smem);

    if (wid < 4) {
        // ---- Embedded W prep (MODE 0, z=0, first 97 CTAs) ----
        if (MODE == 0 && blockIdx.z == 0) {
            const int id = blockIdx.x + (NN / 128) * blockIdx.y;   // 0..127
            if (id < 97) {
                __half* hi = g_Ws + (size_t)id * 64 * 72;
                #pragma unroll
                for (int it = 0; it < 8; ++it) {
                    const int idx = t + it * 128;
                    const int k  = idx >> 4;
                    const int o4 = (idx & 15) * 4;
                    float4 v = make_float4(0.f, 0.f, 0.f, 0.f);
                    if (id < 96) {
                        const int kc = id >> 5, d = id & 31;
                        v = *reinterpret_cast<const float4*>(
                            Wp + ((size_t)(d * KI_ + kc * 64 + k)) * DOUT_ + o4);
                    } else if (k < 32) {
                        v = *reinterpret_cast<const float4*>(biasp + (size_t)k * DOUT_ + o4);
                    }
                    *reinterpret_cast<uint2*>(hi + k * 72 + o4) =
                        make_uint2(pack2h(v.x, v.y), pack2h(v.z, v.w));
                }
                if (t < 64)
                    *reinterpret_cast<uint4*>(hi + t * 72 + 64) = make_uint4(0, 0, 0, 0);
            }
        }

        float acc[2][8][4];
        #pragma unroll
        for (int mt = 0; mt < 2; ++mt)
            #pragma unroll
            for (int nt = 0; nt < 8; ++nt)
                #pragma unroll
                for (int e = 0; e < 4; ++e) acc[mt][nt][e] = 0.f;

        for (int c = 0; c < 8; ++c) {
            const int buf = c & 1;
            const uint32_t base = sb + buf * BUFSZ;
            bar_sync(BAR_FULL + buf);
            mma_chunk_h(acc, base, base + OB_B, wid, lane);
            bar_arrive(BAR_EMPTY + buf);
        }
        const int r0   = rowBlk + wid * 32 + (lane >> 2);
        const int col0 = 2 * (lane & 3);
        #pragma unroll
        for (int mt = 0; mt < 2; ++mt) {
            #pragma unroll
            for (int nt = 0; nt < 8; ++nt) {
                const int row = r0 + mt * 16;
                const int cc  = col0 + nt * 8;
                float2 v0, v1;
                if (MODE == 1) {
                    const float2 s0 = *reinterpret_cast<const float2*>(Sub + (size_t)row * DIN_ + cc);
                    const float2 s1 = *reinterpret_cast<const float2*>(Sub + (size_t)(row + 8) * DIN_ + cc);
                    v0 = make_float2(2.f * acc[mt][nt][0] - s0.x, 2.f * acc[mt][nt][1] - s0.y);
                    v1 = make_float2(2.f * acc[mt][nt][2] - s1.x, 2.f * acc[mt][nt][3] - s1.y);
                } else {
                    v0 = make_float2(acc[mt][nt][0], acc[mt][nt][1]);
                    v1 = make_float2(acc[mt][nt][2], acc[mt][nt][3]);
                }
                *reinterpret_cast<float2*>(C + (size_t)row * DIN_ + cc)       = v0;
                *reinterpret_cast<float2*>(C + (size_t)(row + 8) * DIN_ + cc) = v1;
            }
        }
    } else {
        const int pt = t - 128;
        for (int c = 0; c < 8; ++c) {
            const int buf = c & 1;
            char* baseP = smem + buf * BUFSZ;
            if (c >= 2) bar_sync(BAR_EMPTY + buf);
            #pragma unroll
            for (int q = 0; q < 16; ++q) {
                const int idx = pt + q * 128;
                const int n  = idx >> 4;
                const int j4 = (idx & 15) * 4;
                const float4 v = *reinterpret_cast<const float4*>(
                    A + (size_t)(rowBlk + n) * NN + c * 64 + j4);
                *reinterpret_cast<uint2*>(baseP + n * TSTR + j4 * 2) =
                    make_uint2(pack2h(v.x, v.y), pack2h(v.z, v.w));
            }
            #pragma unroll
            for (int q = 0; q < 8; ++q) {
                const int idx = pt + q * 128;
                const int k  = idx >> 4;
                const int i4 = (idx & 15) * 4;
                const float4 v = *reinterpret_cast<const float4*>(
                    Bm + (size_t)(c * 64 + k) * DIN_ + i4);
                *reinterpret_cast<uint2*>(baseP + OB_B + k * TSTR + i4 * 2) =
                    make_uint2(pack2h(v.x, v.y), pack2h(v.z, v.w));
            }
            bar_arrive(BAR_FULL + buf);
        }
    }
}

// ===========================================================================
// Fused contraction: 64-row CTAs, 2 CTAs/SM, grid 256 (full chip, one wave).
// fin[n,o] = sum_d STE[n,d] * (h @ W[d])[n,o] + (STE @ bias)[n,o]
// A resident (fp16, 64 rows x 224 cols: h 0..191, STE 192..223), per-kc
// register-cached A fragments. B: 6 rotating slots (pairs, 3-pair ring,
// lookahead 2) + slot 6 = bias. 256 threads, 4x2 warp grid (16x32 per warp).
// smem: A 29696 | sT 8192 | B 7x9216 = 102400 B  (x2 CTAs = 204800 < cap)
// ===========================================================================
#define A_STR    464u
#define OFF_ST2  29696
#define OFF_B2   37888
#define BSLOT    9216
#define F_SMEM   102400

__global__ __launch_bounds__(256, 2) void fused_mma(
    const float* __restrict__ STE,
    float* __restrict__ out)
{
    extern __shared__ char smem[];
    const int b     = blockIdx.y;
    const int nBase = blockIdx.x * 64;
    const int t    = threadIdx.x;
    const int wid  = t >> 5;
    const int lane = t & 31;
    const int wy   = wid & 3;      // 4 row groups x 16 rows
    const int wx   = wid >> 2;     // 2 col groups x 32 cols
    const uint32_t sb = smem_u32(smem);
    float* sT = reinterpret_cast<float*>(smem + OFF_ST2);

    // ---- Build static A (fp16): h cols 0..191, STE cols 192..223 ----
    {
        const float* hsrc = g_h + (size_t)b * (CHEB * NN * DIN_);
        #pragma unroll
        for (int it = 0; it < 12; ++it) {
            const int idx = t + it * 256;          // 0..3071 float4s
            const int i4 = (idx & 15) * 4;
            const int n  = (idx >> 4) & 63;
            const int k  = idx >> 10;              // 0..2
            const float4 v = *reinterpret_cast<const float4*>(
                hsrc + ((size_t)k * NN + nBase + n) * DIN_ + i4);
            const uint32_t boff = (uint32_t)n * A_STR + (uint32_t)(k * 64 + i4) * 2u;
            *reinterpret_cast<uint2*>(smem + boff) =
                make_uint2(pack2h(v.x, v.y), pack2h(v.z, v.w));
        }
        const float* ssrc = STE + ((size_t)b * NN + nBase) * ET_;
        #pragma unroll
        for (int it = 0; it < 2; ++it) {
            const int idx = t + it * 256;          // 0..511 float4s
            const int d4 = (idx & 7) * 4;
            const int n  = idx >> 3;               // 0..63
            const float4 v = *reinterpret_cast<const float4*>(ssrc + n * ET_ + d4);
            const uint32_t boff = (uint32_t)n * A_STR + (uint32_t)(192 + d4) * 2u;
            *reinterpret_cast<uint2*>(smem + boff) =
                make_uint2(pack2h(v.x, v.y), pack2h(v.z, v.w));
            sT[(d4 + 0) * 64 + n] = v.x;
            sT[(d4 + 1) * 64 + n] = v.y;
            sT[(d4 + 2) * 64 + n] = v.z;
            sT[(d4 + 3) * 64 + n] = v.w;
        }
    }

    // ---- B tile loader: 576 cp16 per chunk over 256 threads ----
    auto load_chunk = [&](int c, int slot) {
        const uint32_t sbase = sb + OFF_B2 + (uint32_t)slot * BSLOT;
        auto emit = [&](int idx) {
            const int r  = idx / 9;
            const int q9 = idx - r * 9;
            const __half* src = g_Ws + (size_t)c * 4608 + r * 72 + q9 * 8;
            cp16(sbase + (uint32_t)r * TSTR + (uint32_t)q9 * 16u, src);
        };
        emit(t);
        emit(t + 256);
        if (t < 64) emit(512 + t);
    };

    // Prologue: bias -> slot 6; pairs 0,1 -> slots 0..3 (3 groups total)
    load_chunk(96, 6); CP_COMMIT();
    load_chunk(0, 0); load_chunk(1, 1); CP_COMMIT();
    load_chunk(2, 2); load_chunk(3, 3); CP_COMMIT();

    float fin[4][4];
    #pragma unroll
    for (int ng = 0; ng < 4; ++ng)
        #pragma unroll
        for (int e = 0; e < 4; ++e) fin[ng][e] = 0.f;

    const uint32_t rowSel  = (uint32_t)(wy * 16 + (lane & 15));
    const uint32_t kSel    = (uint32_t)((lane >> 4) << 3);
    const uint32_t bRow    = (uint32_t)((lane & 7) + (((lane >> 3) & 1) << 3));
    const uint32_t bColOff = (uint32_t)((wx * 32 + ((lane >> 4) << 3)) * 2);
    const int rl0 = wy * 16 + (lane >> 2);

    uint32_t ahc[4][4];   // cached A fragments: [kstep][4]

    auto do_chunk = [&](int c, int slot) {
        const int kc = c >> 5;
        const int d  = c & 31;
        if (d == 0) {
            #pragma unroll
            for (int ks = 0; ks < 4; ++ks) {
                const uint32_t off = rowSel * A_STR
                                   + (uint32_t)(kc * 64 + ks * 16 + kSel) * 2u;
                ldsm_x4(ahc[ks][0], ahc[ks][1], ahc[ks][2], ahc[ks][3], sb + off);
            }
        }
        const uint32_t bbase = sb + OFF_B2 + (uint32_t)slot * BSLOT;
        float part[4][4];
        #pragma unroll
        for (int ng = 0; ng < 4; ++ng)
            #pragma unroll
            for (int e = 0; e < 4; ++e) part[ng][e] = 0.f;
        #pragma unroll
        for (int ks = 0; ks < 4; ++ks) {
            const uint32_t kb = (uint32_t)(ks * 16);
            #pragma unroll
            for (int g = 0; g < 2; ++g) {
                const uint32_t boff = (kb + bRow) * TSTR + bColOff + (uint32_t)(g * 32);
                uint32_t b0, b1, b2, b3;
                ldsm_x4t(b0, b1, b2, b3, bbase + boff);
                mma_fp16(part[2 * g],     ahc[ks], b0, b1);
                mma_fp16(part[2 * g + 1], ahc[ks], b2, b3);
            }
        }
        const float s0 = sT[d * 64 + rl0];
        const float s1 = sT[d * 64 + rl0 + 8];
        #pragma unroll
        for (int ng = 0; ng < 4; ++ng) {
            fin[ng][0] += s0 * part[ng][0];
            fin[ng][1] += s0 * part[ng][1];
            fin[ng][2] += s1 * part[ng][2];
            fin[ng][3] += s1 * part[ng][3];
        }
    };

    for (int p = 0; p < 48; ++p) {
        CP_WAIT1();              // pair p landed (pair p+1 may still fly)
        __syncthreads();         // pair p-1 consumed by all; safe to refill its slots
        if (p + 2 < 48) {
            load_chunk(2 * p + 4, (2 * p + 4) % 6);
            load_chunk(2 * p + 5, (2 * p + 5) % 6);
        }
        CP_COMMIT();             // unconditional: keep group count aligned
        do_chunk(2 * p,     (2 * p)     % 6);
        do_chunk(2 * p + 1, (2 * p + 1) % 6);
    }

    // ---- Bias chunk c=96 (K=32, A cols 192..223), slot 6, unscaled ----
    {
        const uint32_t bbase = sb + OFF_B2 + 6u * BSLOT;
        #pragma unroll
        for (int ks = 0; ks < 2; ++ks) {
            uint32_t ah[4];
            const uint32_t off = rowSel * A_STR
                               + (uint32_t)(192 + ks * 16 + kSel) * 2u;
            ldsm_x4(ah[0], ah[1], ah[2], ah[3], sb + off);
            const uint32_t kb = (uint32_t)(ks * 16);
            #pragma unroll
            for (int g = 0; g < 2; ++g) {
                const uint32_t boff = (kb + bRow) * TSTR + bColOff + (uint32_t)(g * 32);
                uint32_t b0, b1, b2, b3;
                ldsm_x4t(b0, b1, b2, b3, bbase + boff);
                mma_fp16(fin[2 * g],     ah, b0, b1);
                mma_fp16(fin[2 * g + 1], ah, b2, b3);
            }
        }
    }

    // Epilogue
    const int r0   = nBase + rl0;
    const int col0 = wx * 32 + 2 * (lane & 3);
    float* ob = out + (size_t)b * NN * DOUT_;
    #pragma unroll
    for (int ng = 0; ng < 4; ++ng) {
        const int cc = col0 + ng * 8;
        *reinterpret_cast<float2*>(ob + (size_t)r0 * DOUT_ + cc) =
            make_float2(fin[ng][0], fin[ng][1]);
        *reinterpret_cast<float2*>(ob + (size_t)(r0 + 8) * DOUT_ + cc) =
            make_float2(fin[ng][2], fin[ng][3]);
    }
}

// ===========================================================================
// Launch. Inputs: x, STE, R, SC, weights_pool, bias_pool.
// ===========================================================================
extern "C" void kernel_launch(void* const* d_in, const int* in_sizes, int n_in,
                              void* d_out, int out_size)
{
    (void)in_sizes; (void)n_in; (void)out_size;
    const float* x     = (const float*)d_in[0];
    const float* STE   = (const float*)d_in[1];
    const float* R     = (const float*)d_in[2];
    const float* SC    = (const float*)d_in[3];
    const float* Wp    = (const float*)d_in[4];
    const float* biasp = (const float*)d_in[5];
    float* out = (float*)d_out;

    cudaFuncSetAttribute(prop_mma<0>, cudaFuncAttributeMaxDynamicSharedMemorySize, P_SMEM);
    cudaFuncSetAttribute(prop_mma<1>, cudaFuncAttributeMaxDynamicSharedMemorySize, P_SMEM);
    cudaFuncSetAttribute(fused_mma,   cudaFuncAttributeMaxDynamicSharedMemorySize, F_SMEM);

    prop_mma<0><<<dim3(NN / 128, NB, 2), 256, P_SMEM>>>(R, SC, x, Wp, biasp);
    prop_mma<1><<<dim3(NN / 128, NB, 1), 256, P_SMEM>>>(R, SC, x, Wp, biasp);
    fused_mma<<<dim3(NN / 64, NB), 256, F_SMEM>>>(STE, out);
}

// round 16
// speedup vs baseline: 1.2096x; 1.2096x over previous
#include <cuda_runtime.h>
#include <cuda_bf16.h>
#include <cuda_fp16.h>
#include <cstdint>
#include <cstddef>

// Problem constants
#define NB    32
#define NN    512
#define DIN_  64
#define DOUT_ 64
#define ET_   32
#define CHEB  3
#define KI_   (CHEB * DIN_)   // 192

// Scratch: h[b][k][n][i]  fp16 (6.3 MB)
__device__ __align__(16) __half g_h[(size_t)NB * CHEB * NN * DIN_];
// Pre-converted W (+bias as chunk 96), KC-MAJOR: c = kc*32 + d, bias at 96.
// fp16: [97 chunks][64 rows][72 cols] (144B rows). Written by prop_mma<0>.
__device__ __align__(16) __half g_Ws[97 * 64 * 72];

#define TSTR 144u   // tile row stride bytes (odd multiple of 16B)

// ===========================================================================
// PTX helpers
// ===========================================================================
__device__ __forceinline__ uint32_t smem_u32(const void* p) {
    uint32_t a;
    asm("{ .reg .u64 t; cvta.to.shared.u64 t, %1; cvt.u32.u64 %0, t; }"
        : "=r"(a) : "l"(p));
    return a;
}
__device__ __forceinline__ void ldsm_x4(uint32_t& r0, uint32_t& r1,
                                        uint32_t& r2, uint32_t& r3, uint32_t addr) {
    asm volatile("ldmatrix.sync.aligned.m8n8.x4.shared.b16 {%0,%1,%2,%3}, [%4];"
                 : "=r"(r0), "=r"(r1), "=r"(r2), "=r"(r3) : "r"(addr));
}
__device__ __forceinline__ void ldsm_x4t(uint32_t& r0, uint32_t& r1,
                                         uint32_t& r2, uint32_t& r3, uint32_t addr) {
    asm volatile("ldmatrix.sync.aligned.m8n8.x4.trans.shared.b16 {%0,%1,%2,%3}, [%4];"
                 : "=r"(r0), "=r"(r1), "=r"(r2), "=r"(r3) : "r"(addr));
}
__device__ __forceinline__ void mma_fp16(float* c, const uint32_t* a,
                                         uint32_t b0, uint32_t b1) {
    asm volatile(
        "mma.sync.aligned.m16n8k16.row.col.f32.f16.f16.f32 "
        "{%0,%1,%2,%3}, {%4,%5,%6,%7}, {%8,%9}, {%0,%1,%2,%3};"
        : "+f"(c[0]), "+f"(c[1]), "+f"(c[2]), "+f"(c[3])
        : "r"(a[0]), "r"(a[1]), "r"(a[2]), "r"(a[3]), "r"(b0), "r"(b1));
}
__device__ __forceinline__ void cp16(uint32_t dst, const void* src) {
    asm volatile("cp.async.ca.shared.global [%0], [%1], 16;" :: "r"(dst), "l"(src));
}
#define CP_COMMIT() asm volatile("cp.async.commit_group;" ::: "memory")
#define CP_WAIT2()  asm volatile("cp.async.wait_group 2;" ::: "memory")
__device__ __forceinline__ void bar_sync(int id) {
    asm volatile("bar.sync %0, 256;" :: "r"(id) : "memory");
}
__device__ __forceinline__ void bar_arrive(int id) {
    asm volatile("bar.arrive %0, 256;" :: "r"(id) : "memory");
}
#define BAR_FULL  1
#define BAR_EMPTY 3

// fp16 pack
__device__ __forceinline__ uint32_t pack2h(float p0, float p1) {
    uint32_t r;
    asm("cvt.rn.f16x2.f32 %0, %1, %2;" : "=r"(r) : "f"(p1), "f"(p0));
    return r;
}

// ===========================================================================
// Prop kernels: single-product fp16, warp-specialized, 2 CTAs/SM.
// C[512x64] = A[512x512] @ Bm[512x64]; C stored fp16 into g_h.
// MODE 0: z selects SC->h0 / R->h1, Bm = x (fp32); also converts W tiles.
// MODE 1: A=R, Bm = h1 (fp16, raw copy), C = 2*acc - h0 (h0 read fp16).
// smem: 2 buffers x {A 18432 | B 9216} = 55296 B
// ===========================================================================
#define BUFSZ   27648
#define OB_B    18432
#define P_SMEM  (2 * BUFSZ)

__device__ __forceinline__ void mma_chunk_h(float acc[2][8][4],
                                            uint32_t aBase, uint32_t bBase,
                                            int warp, int lane) {
    const uint32_t rowSel = (uint32_t)(warp * 32 + (lane & 15));
    const uint32_t kSel   = (uint32_t)((lane >> 4) << 3);
    const uint32_t bRow   = (uint32_t)((lane & 7) + (((lane >> 3) & 1) << 3));
    const uint32_t bCol   = (uint32_t)((lane >> 4) << 3);
    #pragma unroll
    for (int ks = 0; ks < 4; ++ks) {
        const uint32_t kb = (uint32_t)(ks * 16);
        uint32_t ah[2][4];
        #pragma unroll
        for (int mt = 0; mt < 2; ++mt) {
            const uint32_t off = (rowSel + (uint32_t)(mt * 16)) * TSTR + (kb + kSel) * 2u;
            ldsm_x4(ah[mt][0], ah[mt][1], ah[mt][2], ah[mt][3], aBase + off);
        }
        #pragma unroll
        for (int g = 0; g < 4; ++g) {
            const uint32_t boff = (kb + bRow) * TSTR + ((uint32_t)(g * 16) + bCol) * 2u;
            uint32_t b0, b1, b2, b3;
            ldsm_x4t(b0, b1, b2, b3, bBase + boff);
            #pragma unroll
            for (int mt = 0; mt < 2; ++mt) {
                mma_fp16(acc[mt][2 * g],     ah[mt], b0, b1);
                mma_fp16(acc[mt][2 * g + 1], ah[mt], b2, b3);
            }
        }
    }
}

template<int MODE>
__global__ __launch_bounds__(256, 2) void prop_mma(
    const float* __restrict__ R,
    const float* __restrict__ SC,
    const float* __restrict__ X,
    const float* __restrict__ Wp,
    const float* __restrict__ biasp)
{
    extern __shared__ char smem[];
    const int b = blockIdx.y;
    const int rowBlk = blockIdx.x * 128;

    __half* hb = g_h + (size_t)b * (CHEB * NN * DIN_);
    const float* A;
    const float* BmF = nullptr;      // MODE 0 source (fp32 x)
    const __half* BmH = nullptr;     // MODE 1 source (fp16 h1)
    const __half* Sub = nullptr;
    __half* C;
    if (MODE == 0) {
        const int which = blockIdx.z;
        A   = (which == 0 ? SC : R) + (size_t)b * NN * NN;
        BmF = X + (size_t)b * NN * DIN_;
        C   = hb + (size_t)which * NN * DIN_;
    } else {
        A   = R  + (size_t)b * NN * NN;
        BmH = hb + (size_t)1 * NN * DIN_;
        Sub = hb + (size_t)0 * NN * DIN_;
        C   = hb + (size_t)2 * NN * DIN_;
    }

    const int t    = threadIdx.x;
    const int wid  = t >> 5;
    const int lane = t & 31;
    const uint32_t sb = smem_u32(smem);

    if (wid < 4) {
        // ---- Embedded W prep (MODE 0, z=0, first 97 CTAs) ----
        if (MODE == 0 && blockIdx.z == 0) {
            const int id = blockIdx.x + (NN / 128) * blockIdx.y;   // 0..127
            if (id < 97) {
                __half* hi = g_Ws + (size_t)id * 64 * 72;
                #pragma unroll
                for (int it = 0; it < 8; ++it) {
                    const int idx = t + it * 128;
                    const int k  = idx >> 4;
                    const int o4 = (idx & 15) * 4;
                    float4 v = make_float4(0.f, 0.f, 0.f, 0.f);
                    if (id < 96) {
                        const int kc = id >> 5, d = id & 31;
                        v = *reinterpret_cast<const float4*>(
                            Wp + ((size_t)(d * KI_ + kc * 64 + k)) * DOUT_ + o4);
                    } else if (k < 32) {
                        v = *reinterpret_cast<const float4*>(biasp + (size_t)k * DOUT_ + o4);
                    }
                    *reinterpret_cast<uint2*>(hi + k * 72 + o4) =
                        make_uint2(pack2h(v.x, v.y), pack2h(v.z, v.w));
                }
                if (t < 64)
                    *reinterpret_cast<uint4*>(hi + t * 72 + 64) = make_uint4(0, 0, 0, 0);
            }
        }

        float acc[2][8][4];
        #pragma unroll
        for (int mt = 0; mt < 2; ++mt)
            #pragma unroll
            for (int nt = 0; nt < 8; ++nt)
                #pragma unroll
                for (int e = 0; e < 4; ++e) acc[mt][nt][e] = 0.f;

        for (int c = 0; c < 8; ++c) {
            const int buf = c & 1;
            const uint32_t base = sb + buf * BUFSZ;
            bar_sync(BAR_FULL + buf);
            mma_chunk_h(acc, base, base + OB_B, wid, lane);
            bar_arrive(BAR_EMPTY + buf);
        }
        // Epilogue: store fp16 (pairs). MODE 1 subtracts fp16 h0.
        const int r0   = rowBlk + wid * 32 + (lane >> 2);
        const int col0 = 2 * (lane & 3);
        #pragma unroll
        for (int mt = 0; mt < 2; ++mt) {
            #pragma unroll
            for (int nt = 0; nt < 8; ++nt) {
                const int row = r0 + mt * 16;
                const int cc  = col0 + nt * 8;
                float p0 = acc[mt][nt][0], p1 = acc[mt][nt][1];
                float p2 = acc[mt][nt][2], p3 = acc[mt][nt][3];
                if (MODE == 1) {
                    const __half2 s0 = *reinterpret_cast<const __half2*>(
                        Sub + (size_t)row * DIN_ + cc);
                    const __half2 s1 = *reinterpret_cast<const __half2*>(
                        Sub + (size_t)(row + 8) * DIN_ + cc);
                    p0 = 2.f * p0 - __half2float(s0.x);
                    p1 = 2.f * p1 - __half2float(s0.y);
                    p2 = 2.f * p2 - __half2float(s1.x);
                    p3 = 2.f * p3 - __half2float(s1.y);
                }
                *reinterpret_cast<uint32_t*>(C + (size_t)row * DIN_ + cc)       = pack2h(p0, p1);
                *reinterpret_cast<uint32_t*>(C + (size_t)(row + 8) * DIN_ + cc) = pack2h(p2, p3);
            }
        }
    } else {
        // ---------------- producer ----------------
        const int pt = t - 128;
        for (int c = 0; c < 8; ++c) {
            const int buf = c & 1;
            char* baseP = smem + buf * BUFSZ;
            if (c >= 2) bar_sync(BAR_EMPTY + buf);
            // A chunk [128 n][64 k]: fp32 -> fp16 pack (R/SC always fp32)
            #pragma unroll
            for (int q = 0; q < 16; ++q) {
                const int idx = pt + q * 128;
                const int n  = idx >> 4;
                const int j4 = (idx & 15) * 4;
                const float4 v = *reinterpret_cast<const float4*>(
                    A + (size_t)(rowBlk + n) * NN + c * 64 + j4);
                *reinterpret_cast<uint2*>(baseP + n * TSTR + j4 * 2) =
                    make_uint2(pack2h(v.x, v.y), pack2h(v.z, v.w));
            }
            // B chunk [64 k][64 i]
            if (MODE == 0) {
                #pragma unroll
                for (int q = 0; q < 8; ++q) {
                    const int idx = pt + q * 128;
                    const int k  = idx >> 4;
                    const int i4 = (idx & 15) * 4;
                    const float4 v = *reinterpret_cast<const float4*>(
                        BmF + (size_t)(c * 64 + k) * DIN_ + i4);
                    *reinterpret_cast<uint2*>(baseP + OB_B + k * TSTR + i4 * 2) =
                        make_uint2(pack2h(v.x, v.y), pack2h(v.z, v.w));
                }
            } else {
                // h1 already fp16: raw 16B copies (512 chunks, 4/thread)
                #pragma unroll
                for (int q = 0; q < 4; ++q) {
                    const int idx = pt + q * 128;      // 0..511
                    const int k   = idx >> 3;
                    const int seg = idx & 7;
                    const uint4 v = *reinterpret_cast<const uint4*>(
                        BmH + (size_t)(c * 64 + k) * DIN_ + seg * 8);
                    *reinterpret_cast<uint4*>(baseP + OB_B + k * TSTR + seg * 16) = v;
                }
            }
            bar_arrive(BAR_FULL + buf);
        }
    }
}

// ===========================================================================
// Fused contraction (round-13 engine): single-product fp16, TRIPLE-chunk.
// fin[n,o] = sum_d STE[n,d] * (h @ W[d])[n,o] + (STE @ bias)[n,o]
// A resident (fp16, cols 0..191 h — raw copy from fp16 g_h — and
// 192..223 STE), per-kc register-cached A fragments. B: 12 rotating slots
// (trips of 3, slot = c % 12, lookahead 3 trips) + slot 12 = bias.
// 512 threads, 4x4 warp grid. smem: A 59392 | sT 16384 | B 13x9216 = 195584
// ===========================================================================
#define A_STR    464u
#define OFF_ST2  59392
#define OFF_B2   75776
#define BSLOT    9216
#define F_SMEM   195584

__global__ __launch_bounds__(512, 1) void fused_mma(
    const float* __restrict__ STE,
    float* __restrict__ out)
{
    extern __shared__ char smem[];
    const int b     = blockIdx.y;
    const int nBase = blockIdx.x * 128;
    const int t    = threadIdx.x;
    const int wid  = t >> 5;
    const int lane = t & 31;
    const int wy   = wid & 3;
    const int wx   = wid >> 2;
    const uint32_t sb = smem_u32(smem);
    float* sT = reinterpret_cast<float*>(smem + OFF_ST2);

    // ---- Build static A: h (fp16 raw copy) cols 0..191, STE cols 192..223 ----
    {
        const __half* hsrc = g_h + (size_t)b * (CHEB * NN * DIN_);
        #pragma unroll
        for (int it = 0; it < 6; ++it) {
            const int idx = t + it * 512;          // 0..3071 16B-chunks
            const int seg = idx & 7;               // 0..7 (8 x 16B per 128B row)
            const int n   = (idx >> 3) & 127;
            const int k   = idx >> 10;             // 0..2
            const uint4 v = *reinterpret_cast<const uint4*>(
                hsrc + ((size_t)k * NN + nBase + n) * DIN_ + seg * 8);
            const uint32_t boff = (uint32_t)n * A_STR + (uint32_t)(k * 64 + seg * 8) * 2u;
            *reinterpret_cast<uint4*>(smem + boff) = v;
        }
        const float* ssrc = STE + ((size_t)b * NN + nBase) * ET_;
        #pragma unroll
        for (int it = 0; it < 2; ++it) {
            const int idx = t + it * 512;          // 0..1023 float4s
            const int d4 = (idx & 7) * 4;
            const int n  = idx >> 3;
            const float4 v = *reinterpret_cast<const float4*>(ssrc + n * ET_ + d4);
            const uint32_t boff = (uint32_t)n * A_STR + (uint32_t)(192 + d4) * 2u;
            *reinterpret_cast<uint2*>(smem + boff) =
                make_uint2(pack2h(v.x, v.y), pack2h(v.z, v.w));
            sT[(d4 + 0) * 128 + n] = v.x;
            sT[(d4 + 1) * 128 + n] = v.y;
            sT[(d4 + 2) * 128 + n] = v.z;
            sT[(d4 + 3) * 128 + n] = v.w;
        }
    }

    auto load_chunk = [&](int c, int slot) {
        const uint32_t sbase = sb + OFF_B2 + (uint32_t)slot * BSLOT;
        auto emit = [&](int idx) {
            const int r  = idx / 9;
            const int q9 = idx - r * 9;
            const __half* src = g_Ws + (size_t)c * 4608 + r * 72 + q9 * 8;
            cp16(sbase + (uint32_t)r * TSTR + (uint32_t)q9 * 16u, src);
        };
        emit(t);
        if (t < 64) emit(512 + t);
    };

    // Prologue: bias -> slot 12 (group 0); trips 0..2 -> slots 0..8
    load_chunk(96, 12); CP_COMMIT();
    #pragma unroll
    for (int p = 0; p < 3; ++p) {
        load_chunk(3 * p,     (3 * p)     % 12);
        load_chunk(3 * p + 1, (3 * p + 1) % 12);
        load_chunk(3 * p + 2, (3 * p + 2) % 12);
        CP_COMMIT();
    }

    float fin[2][2][4];
    #pragma unroll
    for (int mt = 0; mt < 2; ++mt)
        #pragma unroll
        for (int ng = 0; ng < 2; ++ng)
            #pragma unroll
            for (int e = 0; e < 4; ++e) fin[mt][ng][e] = 0.f;

    const uint32_t rowSel  = (uint32_t)(wy * 32 + (lane & 15));
    const uint32_t kSel    = (uint32_t)((lane >> 4) << 3);
    const uint32_t bRow    = (uint32_t)((lane & 7) + (((lane >> 3) & 1) << 3));
    const uint32_t bColOff = (uint32_t)((wx * 16 + ((lane >> 4) << 3)) * 2);
    const int rl0 = wy * 32 + (lane >> 2);

    uint32_t ahc[4][2][4];

    auto do_chunk = [&](int c, int slot) {
        const int kc = c >> 5;
        const int d  = c & 31;
        if (d == 0) {
            #pragma unroll
            for (int ks = 0; ks < 4; ++ks)
                #pragma unroll
                for (int mt = 0; mt < 2; ++mt) {
                    const uint32_t off = (rowSel + (uint32_t)(mt * 16)) * A_STR
                                       + (uint32_t)(kc * 64 + ks * 16 + kSel) * 2u;
                    ldsm_x4(ahc[ks][mt][0], ahc[ks][mt][1],
                            ahc[ks][mt][2], ahc[ks][mt][3], sb + off);
                }
        }
        const uint32_t bbase = sb + OFF_B2 + (uint32_t)slot * BSLOT;
        float part[2][2][4];
        #pragma unroll
        for (int mt = 0; mt < 2; ++mt)
            #pragma unroll
            for (int ng = 0; ng < 2; ++ng)
                #pragma unroll
                for (int e = 0; e < 4; ++e) part[mt][ng][e] = 0.f;
        #pragma unroll
        for (int ks = 0; ks < 4; ++ks) {
            const uint32_t boff = ((uint32_t)(ks * 16) + bRow) * TSTR + bColOff;
            uint32_t b0, b1, b2, b3;
            ldsm_x4t(b0, b1, b2, b3, bbase + boff);
            #pragma unroll
            for (int mt = 0; mt < 2; ++mt) {
                mma_fp16(part[mt][0], ahc[ks][mt], b0, b1);
                mma_fp16(part[mt][1], ahc[ks][mt], b2, b3);
            }
        }
        #pragma unroll
        for (int mt = 0; mt < 2; ++mt) {
            const float s0 = sT[d * 128 + rl0 + mt * 16];
            const float s1 = sT[d * 128 + rl0 + mt * 16 + 8];
            #pragma unroll
            for (int ng = 0; ng < 2; ++ng) {
                fin[mt][ng][0] += s0 * part[mt][ng][0];
                fin[mt][ng][1] += s0 * part[mt][ng][1];
                fin[mt][ng][2] += s1 * part[mt][ng][2];
                fin[mt][ng][3] += s1 * part[mt][ng][3];
            }
        }
    };

    // 32 trips of 3 chunks; slots hold trips p-1..p+2 at iteration start.
    for (int p = 0; p < 32; ++p) {
        CP_WAIT2();              // trip p landed (trips p+1, p+2 may fly)
        __syncthreads();         // trip p-1 consumed by all; safe to refill
        if (p + 3 < 32) {
            const int c0 = 3 * (p + 3);
            load_chunk(c0,     c0 % 12);
            load_chunk(c0 + 1, (c0 + 1) % 12);
            load_chunk(c0 + 2, (c0 + 2) % 12);
        }
        CP_COMMIT();             // unconditional: keep group count aligned
        const int cb = 3 * p;
        do_chunk(cb,     cb % 12);
        do_chunk(cb + 1, (cb + 1) % 12);
        do_chunk(cb + 2, (cb + 2) % 12);
    }

    // ---- Bias chunk c=96 (K=32, A cols 192..223), slot 12, unscaled ----
    {
        const uint32_t bbase = sb + OFF_B2 + 12u * BSLOT;
        #pragma unroll
        for (int ks = 0; ks < 2; ++ks) {
            uint32_t ah[2][4];
            #pragma unroll
            for (int mt = 0; mt < 2; ++mt) {
                const uint32_t off = (rowSel + (uint32_t)(mt * 16)) * A_STR
                                   + (uint32_t)(192 + ks * 16 + kSel) * 2u;
                ldsm_x4(ah[mt][0], ah[mt][1], ah[mt][2], ah[mt][3], sb + off);
            }
            const uint32_t boff = ((uint32_t)(ks * 16) + bRow) * TSTR + bColOff;
            uint32_t b0, b1, b2, b3;
            ldsm_x4t(b0, b1, b2, b3, bbase + boff);
            #pragma unroll
            for (int mt = 0; mt < 2; ++mt) {
                mma_fp16(fin[mt][0], ah[mt], b0, b1);
                mma_fp16(fin[mt][1], ah[mt], b2, b3);
            }
        }
    }

    // Epilogue
    const int r0   = nBase + rl0;
    const int col0 = wx * 16 + 2 * (lane & 3);
    float* ob = out + (size_t)b * NN * DOUT_;
    #pragma unroll
    for (int mt = 0; mt < 2; ++mt) {
        #pragma unroll
        for (int ng = 0; ng < 2; ++ng) {
            const int row = r0 + mt * 16;
            const int cc  = col0 + ng * 8;
            *reinterpret_cast<float2*>(ob + (size_t)row * DOUT_ + cc) =
                make_float2(fin[mt][ng][0], fin[mt][ng][1]);
            *reinterpret_cast<float2*>(ob + (size_t)(row + 8) * DOUT_ + cc) =
                make_float2(fin[mt][ng][2], fin[mt][ng][3]);
        }
    }
}

// ===========================================================================
// Launch. Inputs: x, STE, R, SC, weights_pool, bias_pool.
// ===========================================================================
extern "C" void kernel_launch(void* const* d_in, const int* in_sizes, int n_in,
                              void* d_out, int out_size)
{
    (void)in_sizes; (void)n_in; (void)out_size;
    const float* x     = (const float*)d_in[0];
    const float* STE   = (const float*)d_in[1];
    const float* R     = (const float*)d_in[2];
    const float* SC    = (const float*)d_in[3];
    const float* Wp    = (const float*)d_in[4];
    const float* biasp = (const float*)d_in[5];
    float* out = (float*)d_out;

    cudaFuncSetAttribute(prop_mma<0>, cudaFuncAttributeMaxDynamicSharedMemorySize, P_SMEM);
    cudaFuncSetAttribute(prop_mma<1>, cudaFuncAttributeMaxDynamicSharedMemorySize, P_SMEM);
    cudaFuncSetAttribute(fused_mma,   cudaFuncAttributeMaxDynamicSharedMemorySize, F_SMEM);

    prop_mma<0><<<dim3(NN / 128, NB, 2), 256, P_SMEM>>>(R, SC, x, Wp, biasp);
    prop_mma<1><<<dim3(NN / 128, NB, 1), 256, P_SMEM>>>(R, SC, x, Wp, biasp);
    fused_mma<<<dim3(NN / 128, NB), 512, F_SMEM>>>(STE, out);
}